// round 4
// baseline (speedup 1.0000x reference)
#include <cuda_runtime.h>

// Problem constants
#define BATCH 8
#define C1    128
#define C2    256
#define HIN   160
#define HO    80
#define SPIX  (HO*HO)          // 6400
#define NPIX  (BATCH*SPIX)     // 51200
#define K1    (C1*9)           // 1152
#define K3    (C2*9)           // 2304

// Scratch (device globals -> allowed; no runtime allocation)
__device__ float g_h  [BATCH*C2*SPIX];   // SiLU(BN(conv1(x)))  [8,256,80,80]
__device__ float g_off[BATCH*18*SPIX];   // offsets             [8,18,80,80]

// ---------------- packed f32x2 helpers ----------------
__device__ __forceinline__ unsigned long long pack2(float v) {
  unsigned long long r;
  asm("mov.b64 %0, {%1, %1};" : "=l"(r) : "r"(__float_as_uint(v)));
  return r;
}
__device__ __forceinline__ void ffma2(unsigned long long &d,
                                      unsigned long long a,
                                      unsigned long long b) {
  asm("fma.rn.f32x2 %0, %1, %2, %0;" : "+l"(d) : "l"(a), "l"(b));
}
__device__ __forceinline__ float2 unpack2(unsigned long long v) {
  unsigned int lo, hi;
  asm("mov.b64 {%0, %1}, %2;" : "=r"(lo), "=r"(hi) : "l"(v));
  return make_float2(__uint_as_float(lo), __uint_as_float(hi));
}
__device__ __forceinline__ float silu_f(float v) {
  return __fdividef(v, 1.0f + __expf(-v));
}

// =====================================================================
// Kernel 1: conv3x3 stride2 pad1 (C1->C2) + BN1 + SiLU  -> g_h
// Implicit GEMM: M=256 (cout, 64/block), N=51200 (pixels, 256/block), K=1152
// =====================================================================
__global__ __launch_bounds__(256, 2)
void conv1_kernel(const float* __restrict__ x, const float* __restrict__ w,
                  const float* __restrict__ bg, const float* __restrict__ bb,
                  const float* __restrict__ bm, const float* __restrict__ bv)
{
  __shared__ __align__(16) float Xs[32][256];   // [kk][pixel]
  __shared__ float Ws[64][33];                  // [co][kk], padded
  __shared__ int s_boff[256], s_ihb[256], s_iwb[256], s_out[256];

  const int tid = threadIdx.x;
  const int n0  = blockIdx.x * 256;   // pixel tile base (256 | 6400 -> no batch crossing)
  const int m0  = blockIdx.y * 64;    // cout tile base

  {
    int n  = n0 + tid;
    int b  = n / SPIX;
    int r  = n - b * SPIX;
    int oh = r / HO;
    int ow = r - oh * HO;
    s_boff[tid] = b * (C1 * HIN * HIN);
    s_ihb [tid] = 2 * oh - 1;
    s_iwb [tid] = 2 * ow - 1;
    s_out [tid] = b * (C2 * SPIX) + r;
  }
  __syncthreads();

  const int lane = tid & 31;      // pixel group: owns 8 consecutive pixels
  const int cog  = tid >> 5;      // cout group: owns 8 consecutive couts
  const int pb   = lane * 8;

  const int my_boff = s_boff[tid];
  const int my_ihb  = s_ihb [tid];
  const int my_iwb  = s_iwb [tid];

  unsigned long long acc[8][4];
  #pragma unroll
  for (int i = 0; i < 8; i++)
    #pragma unroll
    for (int j = 0; j < 4; j++) acc[i][j] = 0ull;

  for (int k0 = 0; k0 < K1; k0 += 32) {
    // ---- load W tile 64x32 (w is [256][1152] contiguous) ----
    #pragma unroll
    for (int e = tid; e < 64 * 32; e += 256) {
      int co = e >> 5, kk = e & 31;
      Ws[co][kk] = w[(m0 + co) * K1 + k0 + kk];
    }
    // ---- gather X tile 32x256 ----
    #pragma unroll 4
    for (int kk = 0; kk < 32; kk++) {
      int k   = k0 + kk;
      int cin = k / 9;
      int t   = k - cin * 9;
      int kh  = t / 3;
      int kw  = t - kh * 3;
      int ih  = my_ihb + kh;
      int iw  = my_iwb + kw;
      float val = 0.0f;
      if ((unsigned)ih < (unsigned)HIN && (unsigned)iw < (unsigned)HIN)
        val = x[my_boff + cin * (HIN * HIN) + ih * HIN + iw];
      Xs[kk][tid] = val;
    }
    __syncthreads();
    // ---- 64x256 register-tiled FMA (f32x2) ----
    #pragma unroll
    for (int kk = 0; kk < 32; kk++) {
      unsigned long long xp[4];
      const unsigned long long* xr =
          reinterpret_cast<const unsigned long long*>(&Xs[kk][pb]);
      xp[0] = xr[0]; xp[1] = xr[1]; xp[2] = xr[2]; xp[3] = xr[3];
      #pragma unroll
      for (int i = 0; i < 8; i++) {
        unsigned long long wp = pack2(Ws[cog * 8 + i][kk]);
        ffma2(acc[i][0], wp, xp[0]);
        ffma2(acc[i][1], wp, xp[1]);
        ffma2(acc[i][2], wp, xp[2]);
        ffma2(acc[i][3], wp, xp[3]);
      }
    }
    __syncthreads();
  }

  // ---- epilogue: BN + SiLU, write g_h ----
  #pragma unroll
  for (int i = 0; i < 8; i++) {
    int co = m0 + cog * 8 + i;
    float s  = bg[co] * rsqrtf(bv[co] + 1e-5f);
    float sh = bb[co] - bm[co] * s;
    #pragma unroll
    for (int j = 0; j < 4; j++) {
      float2 v = unpack2(acc[i][j]);
      float a0 = fmaf(v.x, s, sh);
      float a1 = fmaf(v.y, s, sh);
      g_h[s_out[pb + 2 * j    ] + co * SPIX] = silu_f(a0);
      g_h[s_out[pb + 2 * j + 1] + co * SPIX] = silu_f(a1);
    }
  }
}

// =====================================================================
// Kernel 2: offset conv3x3 s1 p1 (C2->18) + bias -> g_off
// M=18 (as 9 f32x2 pairs), N tile = 256 pixels, K=2304
// =====================================================================
__global__ __launch_bounds__(256)
void offs_kernel(const float* __restrict__ w, const float* __restrict__ bias)
{
  __shared__ __align__(16) float Ws[16][18];    // [kk][co], row = 72B (8-aligned)
  __shared__ __align__(16) float Xs[16][256];
  __shared__ int s_hb[256], s_ihb[256], s_iwb[256], s_r[256];

  const int tid = threadIdx.x;
  const int n0  = blockIdx.x * 256;
  {
    int n  = n0 + tid;
    int b  = n / SPIX;
    int r  = n - b * SPIX;
    int oh = r / HO, ow = r - oh * HO;
    s_hb [tid] = b * (C2 * SPIX);
    s_ihb[tid] = oh - 1;
    s_iwb[tid] = ow - 1;
    s_r  [tid] = b * (18 * SPIX) + r;
  }
  __syncthreads();
  const int my_hb = s_hb[tid], my_ihb = s_ihb[tid], my_iwb = s_iwb[tid];
  const int my_r  = s_r[tid];

  unsigned long long acc[9];
  #pragma unroll
  for (int i = 0; i < 9; i++) acc[i] = 0ull;

  for (int k0 = 0; k0 < K3; k0 += 16) {
    for (int e = tid; e < 18 * 16; e += 256) {
      int co = e >> 4, kk = e & 15;
      Ws[kk][co] = w[co * K3 + k0 + kk];
    }
    #pragma unroll 4
    for (int kk = 0; kk < 16; kk++) {
      int k  = k0 + kk;
      int ci = k / 9;
      int t  = k - ci * 9;
      int kh = t / 3, kw = t - kh * 3;
      int ih = my_ihb + kh, iw = my_iwb + kw;
      float val = 0.0f;
      if ((unsigned)ih < (unsigned)HO && (unsigned)iw < (unsigned)HO)
        val = g_h[my_hb + ci * SPIX + ih * HO + iw];
      Xs[kk][tid] = val;
    }
    __syncthreads();
    #pragma unroll
    for (int kk = 0; kk < 16; kk++) {
      unsigned long long xp = pack2(Xs[kk][tid]);
      const unsigned long long* wr =
          reinterpret_cast<const unsigned long long*>(&Ws[kk][0]);
      #pragma unroll
      for (int i = 0; i < 9; i++) ffma2(acc[i], wr[i], xp);
    }
    __syncthreads();
  }

  #pragma unroll
  for (int i = 0; i < 9; i++) {
    float2 v = unpack2(acc[i]);
    g_off[my_r + (2 * i    ) * SPIX] = v.x + bias[2 * i    ];
    g_off[my_r + (2 * i + 1) * SPIX] = v.y + bias[2 * i + 1];
  }
}

// =====================================================================
// Kernel 3: deformable conv3x3 + BN2 + SiLU -> out
// Block: all 256 couts x 64 pixels, K=2304 ((ci,tap) with tap inner).
// Bilinear corner tables (clamped index + masked weight) built once/block.
// =====================================================================
__global__ __launch_bounds__(256, 2)
void deform_kernel(const float* __restrict__ w,
                   const float* __restrict__ bg, const float* __restrict__ bb,
                   const float* __restrict__ bm, const float* __restrict__ bv,
                   float* __restrict__ out)
{
  __shared__ float Ws[256][17];                   // [co][kk], padded
  __shared__ __align__(16) float Xs[16][64];      // [kk][pixel]
  __shared__ __align__(16) int   t_off[9][64][4]; // clamped y*80+x per corner
  __shared__ __align__(16) float t_wt [9][64][4]; // masked bilinear weights
  __shared__ int s_pb[64], s_oi[64];

  const int tid = threadIdx.x;
  const int n0  = blockIdx.x * 64;   // 64 | 6400 -> no batch crossing

  if (tid < 64) {
    int n = n0 + tid;
    int b = n / SPIX;
    int r = n - b * SPIX;
    s_pb[tid] = b * (C2 * SPIX);
    s_oi[tid] = b * (C2 * SPIX) + r;
  }
  for (int e = tid; e < 9 * 64; e += 256) {
    int tap = e >> 6;
    int p   = e & 63;
    int n   = n0 + p;
    int b   = n / SPIX;
    int r   = n - b * SPIX;
    int oh  = r / HO, ow = r - oh * HO;
    int kh  = tap / 3, kw = tap - kh * 3;
    float dy = g_off[(b * 18 + 2 * tap    ) * SPIX + r];
    float dx = g_off[(b * 18 + 2 * tap + 1) * SPIX + r];
    float py = (float)(oh + kh - 1) + dy;
    float px = (float)(ow + kw - 1) + dx;
    float fy = floorf(py), fx = floorf(px);
    int   y0 = (int)fy,    x0 = (int)fx;
    float wy1 = py - fy, wx1 = px - fx;
    float wy0 = 1.0f - wy1, wx0 = 1.0f - wx1;
    #pragma unroll
    for (int q = 0; q < 4; q++) {
      int yy = y0 + (q >> 1);
      int xx = x0 + (q & 1);
      float wq = ((q >> 1) ? wy1 : wy0) * ((q & 1) ? wx1 : wx0);
      bool ok = (yy >= 0) && (yy < HO) && (xx >= 0) && (xx < HO);
      int yc = min(max(yy, 0), HO - 1);
      int xc = min(max(xx, 0), HO - 1);
      t_off[tap][p][q] = yc * HO + xc;
      t_wt [tap][p][q] = ok ? wq : 0.0f;
    }
  }
  __syncthreads();

  const int lane = tid & 31;
  const int warp = tid >> 5;
  const int co_b = (warp * 4 + (lane >> 3)) * 8;  // 8 consecutive couts
  const int p_b  = (lane & 7) * 8;                // 8 consecutive pixels

  const int gp    = tid & 63;      // gather pixel
  const int gk0   = tid >> 6;      // gather kk start (0..3)
  const int my_pb = s_pb[gp];

  unsigned long long acc[8][4];
  #pragma unroll
  for (int i = 0; i < 8; i++)
    #pragma unroll
    for (int j = 0; j < 4; j++) acc[i][j] = 0ull;

  for (int k0 = 0; k0 < K3; k0 += 16) {
    // ---- W tile: 256x16 (w is [256][2304] with k = ci*9+tap) ----
    #pragma unroll
    for (int e = tid; e < 256 * 16; e += 256) {
      int co = e >> 4, kk = e & 15;
      Ws[co][kk] = w[co * K3 + k0 + kk];
    }
    // ---- X tile via bilinear gather of g_h ----
    #pragma unroll
    for (int kk = gk0; kk < 16; kk += 4) {
      int k   = k0 + kk;
      int ci  = k / 9;
      int tap = k - ci * 9;
      int base = my_pb + ci * SPIX;
      int4   o4 = *reinterpret_cast<const int4*  >(&t_off[tap][gp][0]);
      float4 w4 = *reinterpret_cast<const float4*>(&t_wt [tap][gp][0]);
      float s = w4.x * g_h[base + o4.x]
              + w4.y * g_h[base + o4.y]
              + w4.z * g_h[base + o4.z]
              + w4.w * g_h[base + o4.w];
      Xs[kk][gp] = s;
    }
    __syncthreads();
    // ---- 256x64 tile FMA (f32x2), 8co x 8px per thread ----
    #pragma unroll
    for (int kk = 0; kk < 16; kk++) {
      unsigned long long xp[4];
      const unsigned long long* xr =
          reinterpret_cast<const unsigned long long*>(&Xs[kk][p_b]);
      xp[0] = xr[0]; xp[1] = xr[1]; xp[2] = xr[2]; xp[3] = xr[3];
      #pragma unroll
      for (int i = 0; i < 8; i++) {
        unsigned long long wp = pack2(Ws[co_b + i][kk]);
        ffma2(acc[i][0], wp, xp[0]);
        ffma2(acc[i][1], wp, xp[1]);
        ffma2(acc[i][2], wp, xp[2]);
        ffma2(acc[i][3], wp, xp[3]);
      }
    }
    __syncthreads();
  }

  // ---- epilogue: BN2 + SiLU ----
  #pragma unroll
  for (int i = 0; i < 8; i++) {
    int co = co_b + i;
    float s  = bg[co] * rsqrtf(bv[co] + 1e-5f);
    float sh = bb[co] - bm[co] * s;
    #pragma unroll
    for (int j = 0; j < 4; j++) {
      float2 v = unpack2(acc[i][j]);
      float a0 = fmaf(v.x, s, sh);
      float a1 = fmaf(v.y, s, sh);
      out[s_oi[p_b + 2 * j    ] + co * SPIX] = silu_f(a0);
      out[s_oi[p_b + 2 * j + 1] + co * SPIX] = silu_f(a1);
    }
  }
}

// =====================================================================
extern "C" void kernel_launch(void* const* d_in, const int* in_sizes, int n_in,
                              void* d_out, int out_size) {
  const float* x       = (const float*)d_in[0];
  const float* conv1_w = (const float*)d_in[1];
  const float* bn1_g   = (const float*)d_in[2];
  const float* bn1_b   = (const float*)d_in[3];
  const float* bn1_m   = (const float*)d_in[4];
  const float* bn1_v   = (const float*)d_in[5];
  const float* off_w   = (const float*)d_in[6];
  const float* off_b   = (const float*)d_in[7];
  const float* dconv_w = (const float*)d_in[8];
  const float* bn2_g   = (const float*)d_in[9];
  const float* bn2_b   = (const float*)d_in[10];
  const float* bn2_m   = (const float*)d_in[11];
  const float* bn2_v   = (const float*)d_in[12];
  float* out = (float*)d_out;

  conv1_kernel<<<dim3(NPIX / 256, C2 / 64), 256>>>(x, conv1_w, bn1_g, bn1_b, bn1_m, bn1_v);
  offs_kernel<<<NPIX / 256, 256>>>(off_w, off_b);
  deform_kernel<<<NPIX / 64, 256>>>(dconv_w, bn2_g, bn2_b, bn2_m, bn2_v, out);
}

// round 7
// speedup vs baseline: 2.5658x; 2.5658x over previous
#include <cuda_runtime.h>
#include <cuda_bf16.h>
#include <cstdint>

#define BATCH 8
#define C1    128
#define C2    256
#define HIN   160
#define HO    80
#define SPIX  6400
#define NPIX  51200
#define K1    1152
#define K3    2304

// -------- scratch (device globals; no runtime allocation) --------
__device__ float g_h  [BATCH*C2*SPIX];   // SiLU(BN(conv1(x)))
__device__ float g_off[BATCH*18*SPIX];   // offsets
__device__ __nv_bfloat16 g_w1h[C2*K1];   // conv1 weights, k=tap*128+ci, hi
__device__ __nv_bfloat16 g_w1l[C2*K1];   // lo
__device__ __nv_bfloat16 g_wdh[C2*K3];   // deform weights, k=tap*256+ci, hi
__device__ __nv_bfloat16 g_wdl[C2*K3];   // lo

// -------- helpers --------
__device__ __forceinline__ uint32_t smem_u32(const void* p){
  uint32_t a;
  asm("{ .reg .u64 t; cvta.to.shared.u64 t, %1; cvt.u32.u64 %0, t; }" : "=r"(a) : "l"(p));
  return a;
}
#define SWZ(o) ((o) ^ (((o)>>3)&0x70))

__device__ __forceinline__ void ldsm4(uint32_t* r, uint32_t addr){
  asm volatile("ldmatrix.sync.aligned.m8n8.x4.shared.b16 {%0,%1,%2,%3}, [%4];"
    : "=r"(r[0]),"=r"(r[1]),"=r"(r[2]),"=r"(r[3]) : "r"(addr));
}
__device__ __forceinline__ void ldsm2(uint32_t* r, uint32_t addr){
  asm volatile("ldmatrix.sync.aligned.m8n8.x2.shared.b16 {%0,%1}, [%2];"
    : "=r"(r[0]),"=r"(r[1]) : "r"(addr));
}
__device__ __forceinline__ void mma16816(float* d, const uint32_t* a, const uint32_t* b){
  asm volatile("mma.sync.aligned.m16n8k16.row.col.f32.bf16.bf16.f32 "
    "{%0,%1,%2,%3}, {%4,%5,%6,%7}, {%8,%9}, {%0,%1,%2,%3};"
    : "+f"(d[0]), "+f"(d[1]), "+f"(d[2]), "+f"(d[3])
    : "r"(a[0]), "r"(a[1]), "r"(a[2]), "r"(a[3]), "r"(b[0]), "r"(b[1]));
}

union Pack8 { unsigned short s[8]; uint4 v; };

__device__ __forceinline__ float silu_f(float v) {
  return __fdividef(v, 1.0f + __expf(-v));
}
__device__ __forceinline__ void split_bf16(float v, unsigned short& h, unsigned short& l){
  __nv_bfloat16 hh = __float2bfloat16(v);
  float hf = __bfloat162float(hh);
  __nv_bfloat16 ll = __float2bfloat16(v - hf);
  h = __bfloat16_as_ushort(hh);
  l = __bfloat16_as_ushort(ll);
}

// SMEM layout (byte offsets within dynamic smem)
#define SM_AH    0        // A hi: 256 rows x 128B = 32768
#define SM_AL    32768    // A lo
#define SM_BH    65536    // B hi: 128 rows x 128B = 16384
#define SM_BL    81920    // B lo
#define SM_META  98304    // conv1: ih[128], iw[128]
#define SM_TOF   98304            // deform: t_off 9*128*16 = 18432
#define SM_TWT   (98304+18432)    // deform: t_wt 18432
#define SMEM_CONV1  99328
#define SMEM_DEFORM 135168

// =====================================================================
// Prep: convert+reorder weights to bf16 hi/lo, k = tap*Cin + ci
// =====================================================================
__global__ void prep_kernel(const float* __restrict__ w1, const float* __restrict__ wd)
{
  int stride = gridDim.x * blockDim.x;
  for (int i = blockIdx.x*blockDim.x + threadIdx.x; i < C2*K1; i += stride) {
    int co = i / K1, t = i - co*K1, tap = t >> 7, ci = t & 127;
    float v = w1[(co*C1 + ci)*9 + tap];
    unsigned short h, l; split_bf16(v, h, l);
    g_w1h[i] = __ushort_as_bfloat16(h);
    g_w1l[i] = __ushort_as_bfloat16(l);
  }
  for (int i = blockIdx.x*blockDim.x + threadIdx.x; i < C2*K3; i += stride) {
    int co = i / K3, t = i - co*K3, tap = t >> 8, ci = t & 255;
    float v = wd[(co*C2 + ci)*9 + tap];
    unsigned short h, l; split_bf16(v, h, l);
    g_wdh[i] = __ushort_as_bfloat16(h);
    g_wdl[i] = __ushort_as_bfloat16(l);
  }
}

// =====================================================================
// Shared warp-MMA compute core: one K-chunk of 64 (4 ksteps of 16)
// Warp tile: 64 cout (mbase) x 32 px (nbase). acc d[4][4][4].
// =====================================================================
__device__ __forceinline__ void chunk_mma(uint32_t sb, int mbase, int nbase,
                                          int lane, float d[4][4][4])
{
  const uint32_t a_row  = (uint32_t)(mbase + (lane & 15)) * 128 + ((lane >> 4) & 1) * 16;
  const uint32_t b_row  = (uint32_t)(nbase + (lane & 7)) * 128 + ((lane >> 3) & 1) * 16;
  #pragma unroll
  for (int ks = 0; ks < 4; ks++) {
    uint32_t bh[4][2], bl[4][2];
    #pragma unroll
    for (int nt = 0; nt < 4; nt++) {
      uint32_t bo = SWZ(b_row + nt*8*128 + ks*32);
      ldsm2(bh[nt], sb + SM_BH + bo);
      ldsm2(bl[nt], sb + SM_BL + bo);
    }
    #pragma unroll
    for (int mt = 0; mt < 4; mt++) {
      uint32_t ah[4], al[4];
      uint32_t ao = SWZ(a_row + mt*16*128 + ks*32);
      ldsm4(ah, sb + SM_AH + ao);
      ldsm4(al, sb + SM_AL + ao);
      #pragma unroll
      for (int nt = 0; nt < 4; nt++) {
        mma16816(d[mt][nt], ah, bh[nt]);
        mma16816(d[mt][nt], ah, bl[nt]);
        mma16816(d[mt][nt], al, bh[nt]);
      }
    }
  }
}

// =====================================================================
// Kernel 1: conv3x3 s2 p1 (C1->C2) + BN1 + SiLU -> g_h
// CTA: 256 cout x 128 px, 512 threads (16 warps 4Mx4N). 18 chunks of 64.
// =====================================================================
__global__ __launch_bounds__(512, 1)
void conv1_mma(const float* __restrict__ x,
               const float* __restrict__ bg, const float* __restrict__ bb,
               const float* __restrict__ bm, const float* __restrict__ bv)
{
  extern __shared__ char smem[];
  const uint32_t sb = smem_u32(smem);
  const int tid = threadIdx.x;
  const int n0 = blockIdx.x * 128;
  const int b  = n0 / SPIX;
  const int r0 = n0 - b * SPIX;

  if (tid < 128) {
    int r = r0 + tid, oh = r / HO, ow = r - oh * HO;
    ((int*)(smem + SM_META))[tid]       = 2*oh - 1;
    ((int*)(smem + SM_META + 512))[tid] = 2*ow - 1;
  }
  __syncthreads();

  const int p   = tid & 127;   // gather pixel
  const int cig = tid >> 7;    // gather ci group (0..3)
  const int ihb = ((int*)(smem + SM_META))[p];
  const int iwb = ((int*)(smem + SM_META + 512))[p];
  const float* xb = x + (size_t)b * C1 * HIN * HIN;

  const int lane = tid & 31, wid = tid >> 5;
  const int mbase = (wid >> 2) * 64;
  const int nbase = (wid & 3) * 32;

  float d[4][4][4];
  #pragma unroll
  for (int i = 0; i < 4; i++)
    #pragma unroll
    for (int j = 0; j < 4; j++)
      #pragma unroll
      for (int q = 0; q < 4; q++) d[i][j][q] = 0.0f;

  for (int c = 0; c < 18; c++) {
    const int k0 = c * 64, tap = c >> 1, ci0 = (c & 1) * 64;
    const int kh = tap / 3, kw = tap - 3 * kh;
    // ---- A slice (256 x 64 bf16, hi+lo), swizzled ----
    #pragma unroll
    for (int i = 0; i < 4; i++) {
      int idx = tid + i*512, row = idx >> 3, cc = idx & 7;
      size_t sbyte = ((size_t)row * K1 + k0) * 2 + cc * 16;
      uint32_t doff = SWZ((uint32_t)(row*128 + cc*16));
      *(uint4*)(smem + SM_AH + doff) = *(const uint4*)((const char*)g_w1h + sbyte);
      *(uint4*)(smem + SM_AL + doff) = *(const uint4*)((const char*)g_w1l + sbyte);
    }
    // ---- B slice (128 px x 64 ci, im2col, hi+lo) ----
    const int ih = ihb + kh, iw = iwb + kw;
    const bool okp = ((unsigned)ih < (unsigned)HIN) && ((unsigned)iw < (unsigned)HIN);
    const float* src = xb + ih * HIN + iw;
    #pragma unroll
    for (int g = 0; g < 2; g++) {
      Pack8 hbuf, lbuf;
      #pragma unroll
      for (int j = 0; j < 8; j++) {
        int ci = ci0 + cig*16 + g*8 + j;
        float v = okp ? __ldg(src + (size_t)ci * (HIN*HIN)) : 0.0f;
        split_bf16(v, hbuf.s[j], lbuf.s[j]);
      }
      uint32_t doff = SWZ((uint32_t)(p*128 + cig*32 + g*16));
      *(uint4*)(smem + SM_BH + doff) = hbuf.v;
      *(uint4*)(smem + SM_BL + doff) = lbuf.v;
    }
    __syncthreads();
    chunk_mma(sb, mbase, nbase, lane, d);
    __syncthreads();
  }

  // ---- epilogue: BN1 + SiLU, float2 stores ----
  const int group = lane >> 2, tig = lane & 3;
  float* dst = g_h + (size_t)b * C2 * SPIX;
  #pragma unroll
  for (int mt = 0; mt < 4; mt++) {
    int co0 = mbase + mt*16 + group, co1 = co0 + 8;
    float s0 = bg[co0] * rsqrtf(bv[co0] + 1e-5f), h0 = bb[co0] - bm[co0]*s0;
    float s1 = bg[co1] * rsqrtf(bv[co1] + 1e-5f), h1 = bb[co1] - bm[co1]*s1;
    #pragma unroll
    for (int nt = 0; nt < 4; nt++) {
      int px = r0 + nbase + nt*8 + tig*2;
      float2 v0 = make_float2(silu_f(fmaf(d[mt][nt][0], s0, h0)),
                              silu_f(fmaf(d[mt][nt][1], s0, h0)));
      float2 v1 = make_float2(silu_f(fmaf(d[mt][nt][2], s1, h1)),
                              silu_f(fmaf(d[mt][nt][3], s1, h1)));
      *(float2*)(dst + (size_t)co0 * SPIX + px) = v0;
      *(float2*)(dst + (size_t)co1 * SPIX + px) = v1;
    }
  }
}

// =====================================================================
// Kernel 2: offset conv3x3 s1 p1 (C2->18) + bias -> g_off (scalar f32x2)
// =====================================================================
__device__ __forceinline__ unsigned long long pack2(float v) {
  unsigned long long r;
  asm("mov.b64 %0, {%1, %1};" : "=l"(r) : "r"(__float_as_uint(v)));
  return r;
}
__device__ __forceinline__ void ffma2(unsigned long long &d, unsigned long long a,
                                      unsigned long long b) {
  asm("fma.rn.f32x2 %0, %1, %2, %0;" : "+l"(d) : "l"(a), "l"(b));
}
__device__ __forceinline__ float2 unpack2(unsigned long long v) {
  unsigned int lo, hi;
  asm("mov.b64 {%0, %1}, %2;" : "=r"(lo), "=r"(hi) : "l"(v));
  return make_float2(__uint_as_float(lo), __uint_as_float(hi));
}

__global__ __launch_bounds__(256)
void offs_kernel(const float* __restrict__ w, const float* __restrict__ bias)
{
  __shared__ __align__(16) float Ws[16][18];
  __shared__ __align__(16) float Xs[16][256];
  __shared__ int s_hb[256], s_ihb[256], s_iwb[256], s_r[256];

  const int tid = threadIdx.x;
  const int n0  = blockIdx.x * 256;
  {
    int n  = n0 + tid;
    int b  = n / SPIX;
    int r  = n - b * SPIX;
    int oh = r / HO, ow = r - oh * HO;
    s_hb [tid] = b * (C2 * SPIX);
    s_ihb[tid] = oh - 1;
    s_iwb[tid] = ow - 1;
    s_r  [tid] = b * (18 * SPIX) + r;
  }
  __syncthreads();
  const int my_hb = s_hb[tid], my_ihb = s_ihb[tid], my_iwb = s_iwb[tid];
  const int my_r  = s_r[tid];

  unsigned long long acc[9];
  #pragma unroll
  for (int i = 0; i < 9; i++) acc[i] = 0ull;

  for (int k0 = 0; k0 < K3; k0 += 16) {
    for (int e = tid; e < 18 * 16; e += 256) {
      int co = e >> 4, kk = e & 15;
      Ws[kk][co] = w[co * K3 + k0 + kk];
    }
    #pragma unroll 4
    for (int kk = 0; kk < 16; kk++) {
      int k  = k0 + kk;
      int ci = k / 9;
      int t  = k - ci * 9;
      int kh = t / 3, kw = t - kh * 3;
      int ih = my_ihb + kh, iw = my_iwb + kw;
      float val = 0.0f;
      if ((unsigned)ih < (unsigned)HO && (unsigned)iw < (unsigned)HO)
        val = g_h[my_hb + ci * SPIX + ih * HO + iw];
      Xs[kk][tid] = val;
    }
    __syncthreads();
    #pragma unroll
    for (int kk = 0; kk < 16; kk++) {
      unsigned long long xp = pack2(Xs[kk][tid]);
      const unsigned long long* wr = reinterpret_cast<const unsigned long long*>(&Ws[kk][0]);
      #pragma unroll
      for (int i = 0; i < 9; i++) ffma2(acc[i], wr[i], xp);
    }
    __syncthreads();
  }

  #pragma unroll
  for (int i = 0; i < 9; i++) {
    float2 v = unpack2(acc[i]);
    g_off[my_r + (2 * i    ) * SPIX] = v.x + bias[2 * i    ];
    g_off[my_r + (2 * i + 1) * SPIX] = v.y + bias[2 * i + 1];
  }
}

// =====================================================================
// Kernel 3: deformable conv3x3 + BN2 + SiLU -> out
// CTA: 256 cout x 128 px, 512 threads. 36 chunks of 64 (tap fixed/chunk).
// =====================================================================
__global__ __launch_bounds__(512, 1)
void deform_mma(const float* __restrict__ bg, const float* __restrict__ bb,
                const float* __restrict__ bm, const float* __restrict__ bv,
                float* __restrict__ out)
{
  extern __shared__ char smem[];
  const uint32_t sb = smem_u32(smem);
  const int tid = threadIdx.x;
  const int n0 = blockIdx.x * 128;
  const int b  = n0 / SPIX;
  const int r0 = n0 - b * SPIX;

  // bilinear corner tables per (tap, pixel)
  for (int e = tid; e < 9 * 128; e += 512) {
    int tap = e >> 7, p = e & 127;
    int r = r0 + p;
    int oh = r / HO, ow = r - oh * HO;
    int kh = tap / 3, kw = tap - 3 * kh;
    float dy = g_off[((size_t)b*18 + 2*tap    ) * SPIX + r];
    float dx = g_off[((size_t)b*18 + 2*tap + 1) * SPIX + r];
    float py = (float)(oh + kh - 1) + dy;
    float px = (float)(ow + kw - 1) + dx;
    float fy = floorf(py), fx = floorf(px);
    int   y0 = (int)fy,    x0 = (int)fx;
    float wy1 = py - fy, wx1 = px - fx;
    float wy0 = 1.0f - wy1, wx0 = 1.0f - wx1;
    int*   to = (int*)  (smem + SM_TOF + e*16);
    float* tw = (float*)(smem + SM_TWT + e*16);
    #pragma unroll
    for (int q = 0; q < 4; q++) {
      int yy = y0 + (q >> 1);
      int xx = x0 + (q & 1);
      float wq = ((q >> 1) ? wy1 : wy0) * ((q & 1) ? wx1 : wx0);
      bool okq = (yy >= 0) && (yy < HO) && (xx >= 0) && (xx < HO);
      int yc = min(max(yy, 0), HO - 1);
      int xc = min(max(xx, 0), HO - 1);
      to[q] = yc * HO + xc;
      tw[q] = okq ? wq : 0.0f;
    }
  }
  __syncthreads();

  const int p   = tid & 127;
  const int cig = tid >> 7;
  const float* hbase = g_h + (size_t)b * C2 * SPIX;

  const int lane = tid & 31, wid = tid >> 5;
  const int mbase = (wid >> 2) * 64;
  const int nbase = (wid & 3) * 32;

  float d[4][4][4];
  #pragma unroll
  for (int i = 0; i < 4; i++)
    #pragma unroll
    for (int j = 0; j < 4; j++)
      #pragma unroll
      for (int q = 0; q < 4; q++) d[i][j][q] = 0.0f;

  for (int c = 0; c < 36; c++) {
    const int k0 = c * 64, tap = c >> 2, ci0 = (c & 3) * 64;
    // ---- A slice (256 x 64 bf16, hi+lo) ----
    #pragma unroll
    for (int i = 0; i < 4; i++) {
      int idx = tid + i*512, row = idx >> 3, cc = idx & 7;
      size_t sbyte = ((size_t)row * K3 + k0) * 2 + cc * 16;
      uint32_t doff = SWZ((uint32_t)(row*128 + cc*16));
      *(uint4*)(smem + SM_AH + doff) = *(const uint4*)((const char*)g_wdh + sbyte);
      *(uint4*)(smem + SM_AL + doff) = *(const uint4*)((const char*)g_wdl + sbyte);
    }
    // ---- B slice: bilinear samples of g_h (hi+lo) ----
    const int4   o4 = *(const int4*)  (smem + SM_TOF + (tap*128 + p)*16);
    const float4 w4 = *(const float4*)(smem + SM_TWT + (tap*128 + p)*16);
    #pragma unroll
    for (int g = 0; g < 2; g++) {
      Pack8 hbuf, lbuf;
      #pragma unroll
      for (int j = 0; j < 8; j++) {
        int ci = ci0 + cig*16 + g*8 + j;
        const float* pp = hbase + (size_t)ci * SPIX;
        float v = w4.x * __ldg(pp + o4.x) + w4.y * __ldg(pp + o4.y)
                + w4.z * __ldg(pp + o4.z) + w4.w * __ldg(pp + o4.w);
        split_bf16(v, hbuf.s[j], lbuf.s[j]);
      }
      uint32_t doff = SWZ((uint32_t)(p*128 + cig*32 + g*16));
      *(uint4*)(smem + SM_BH + doff) = hbuf.v;
      *(uint4*)(smem + SM_BL + doff) = lbuf.v;
    }
    __syncthreads();
    chunk_mma(sb, mbase, nbase, lane, d);
    __syncthreads();
  }

  // ---- epilogue: BN2 + SiLU, float2 stores ----
  const int group = lane >> 2, tig = lane & 3;
  float* dst = out + (size_t)b * C2 * SPIX;
  #pragma unroll
  for (int mt = 0; mt < 4; mt++) {
    int co0 = mbase + mt*16 + group, co1 = co0 + 8;
    float s0 = bg[co0] * rsqrtf(bv[co0] + 1e-5f), h0 = bb[co0] - bm[co0]*s0;
    float s1 = bg[co1] * rsqrtf(bv[co1] + 1e-5f), h1 = bb[co1] - bm[co1]*s1;
    #pragma unroll
    for (int nt = 0; nt < 4; nt++) {
      int px = r0 + nbase + nt*8 + tig*2;
      float2 v0 = make_float2(silu_f(fmaf(d[mt][nt][0], s0, h0)),
                              silu_f(fmaf(d[mt][nt][1], s0, h0)));
      float2 v1 = make_float2(silu_f(fmaf(d[mt][nt][2], s1, h1)),
                              silu_f(fmaf(d[mt][nt][3], s1, h1)));
      *(float2*)(dst + (size_t)co0 * SPIX + px) = v0;
      *(float2*)(dst + (size_t)co1 * SPIX + px) = v1;
    }
  }
}

// =====================================================================
extern "C" void kernel_launch(void* const* d_in, const int* in_sizes, int n_in,
                              void* d_out, int out_size) {
  const float* x       = (const float*)d_in[0];
  const float* conv1_w = (const float*)d_in[1];
  const float* bn1_g   = (const float*)d_in[2];
  const float* bn1_b   = (const float*)d_in[3];
  const float* bn1_m   = (const float*)d_in[4];
  const float* bn1_v   = (const float*)d_in[5];
  const float* off_w   = (const float*)d_in[6];
  const float* off_b   = (const float*)d_in[7];
  const float* dconv_w = (const float*)d_in[8];
  const float* bn2_g   = (const float*)d_in[9];
  const float* bn2_b   = (const float*)d_in[10];
  const float* bn2_m   = (const float*)d_in[11];
  const float* bn2_v   = (const float*)d_in[12];
  float* out = (float*)d_out;

  cudaFuncSetAttribute(conv1_mma,  cudaFuncAttributeMaxDynamicSharedMemorySize, SMEM_CONV1);
  cudaFuncSetAttribute(deform_mma, cudaFuncAttributeMaxDynamicSharedMemorySize, SMEM_DEFORM);

  prep_kernel<<<512, 256>>>(conv1_w, dconv_w);
  conv1_mma<<<NPIX / 128, 512, SMEM_CONV1>>>(x, bn1_g, bn1_b, bn1_m, bn1_v);
  offs_kernel<<<NPIX / 256, 256>>>(off_w, off_b);
  deform_mma<<<NPIX / 128, 512, SMEM_DEFORM>>>(bn2_g, bn2_b, bn2_m, bn2_v, out);
}